// round 16
// baseline (speedup 1.0000x reference)
#include <cuda_runtime.h>

// FINAL — interactionModule_77936476554069
// (byte-identical; 8 passing benches, rel_err 0.0 every time, dur
//  {5.06, 5.12, 5.15, 5.63, 5.98, 6.02, 6.11} us; ncu kernel time stable
//  4.29-4.67us and uncorrelated with dur -> the ~1.1us dur spread is
//  harness/container timing noise, not kernel behavior)
//
// Math: reference's zeroPotential makes force = ||dr|| * 0.0 == 0.0f for every
// edge (dr finite, normalize denominator clamped to >=1e-12, so no 0*inf/0*nan
// path). All 6.4M edge messages are exact zeros; segment_sum of zeros is zero.
// Therefore a = -GAMMA * v elementwise over N*D = 200000 floats, bitwise equal
// to the reference. The entire edge gather/normalize/scatter pipeline is elided.
//
// Kernel: 49 blocks x 512 threads = 25088 threads, one 256-bit
// ld.global.nc.v8 + one 256-bit st.global.v8 each (n8 = 25000), single CTA
// wave on 148 SMs.
//
// Session wins: (1) algebraic elision of the edge pipeline (the whole problem);
// (2) sm_100a 256-bit v8 ld/st halving wavefront count (-0.8us). All other
// axes (grid shape x4, per-thread MLP, occupancy, CTA count) measured neutral
// or regressive; remaining wall time is launch ramp + graph replay. Terminal.

#define GAMMA 0.1f

__global__ void __launch_bounds__(512) scale_v_kernel(const float* __restrict__ v,
                                                      float* __restrict__ out,
                                                      int n8) {
    int i = blockIdx.x * 512 + threadIdx.x;
    if (i < n8) {
        const float* src = v + (size_t)i * 8;
        float* dst = out + (size_t)i * 8;
        float a0, a1, a2, a3, a4, a5, a6, a7;
        asm volatile(
            "ld.global.nc.v8.f32 {%0,%1,%2,%3,%4,%5,%6,%7}, [%8];"
            : "=f"(a0), "=f"(a1), "=f"(a2), "=f"(a3),
              "=f"(a4), "=f"(a5), "=f"(a6), "=f"(a7)
            : "l"(src));
        a0 = -GAMMA * a0; a1 = -GAMMA * a1; a2 = -GAMMA * a2; a3 = -GAMMA * a3;
        a4 = -GAMMA * a4; a5 = -GAMMA * a5; a6 = -GAMMA * a6; a7 = -GAMMA * a7;
        asm volatile(
            "st.global.v8.f32 [%0], {%1,%2,%3,%4,%5,%6,%7,%8};"
            :: "l"(dst),
               "f"(a0), "f"(a1), "f"(a2), "f"(a3),
               "f"(a4), "f"(a5), "f"(a6), "f"(a7)
            : "memory");
    }
}

// Tail safety for out_size % 8 != 0 (not hit for this shape: 200000 % 8 == 0).
__global__ void scale_v_tail_kernel(const float* __restrict__ v,
                                    float* __restrict__ out,
                                    int start, int n) {
    int i = start + blockIdx.x * blockDim.x + threadIdx.x;
    if (i < n) out[i] = -GAMMA * v[i];
}

extern "C" void kernel_launch(void* const* d_in, const int* in_sizes, int n_in,
                              void* d_out, int out_size) {
    // metadata order: x, v, src, dst
    const float* v = (const float*)d_in[1];
    float* out = (float*)d_out;

    int n = out_size;      // 200000
    int n8 = n / 8;        // 25000
    int tail = n - n8 * 8; // 0 for this shape

    const int TPB = 512;
    if (n8 > 0) {
        int blocks = (n8 + TPB - 1) / TPB;   // 49 -> single wave
        scale_v_kernel<<<blocks, TPB>>>(v, out, n8);
    }
    if (tail > 0) {
        int blocks = (tail + 255) / 256;
        scale_v_tail_kernel<<<blocks, 256>>>(v, out, n8 * 8, n);
    }
}

// round 17
// speedup vs baseline: 1.1143x; 1.1143x over previous
#include <cuda_runtime.h>

// FINAL — interactionModule_77936476554069
// (byte-identical; 9 passing benches, rel_err 0.0 every time, dur
//  {5.06, 5.12, 5.15, 5.63, 5.98, 6.02, 6.11, 6.24} us; ncu kernel time
//  stable 4.29-4.67us and uncorrelated with dur -> the ~1.2us dur spread is
//  harness/container timing noise, not kernel behavior)
//
// Math: reference's zeroPotential makes force = ||dr|| * 0.0 == 0.0f for every
// edge (dr finite, normalize denominator clamped to >=1e-12, so no 0*inf/0*nan
// path). All 6.4M edge messages are exact zeros; segment_sum of zeros is zero.
// Therefore a = -GAMMA * v elementwise over N*D = 200000 floats, bitwise equal
// to the reference. The entire edge gather/normalize/scatter pipeline is elided.
//
// Kernel: 49 blocks x 512 threads = 25088 threads, one 256-bit
// ld.global.nc.v8 + one 256-bit st.global.v8 each (n8 = 25000), single CTA
// wave on 148 SMs.
//
// Session wins: (1) algebraic elision of the edge pipeline (the whole problem);
// (2) sm_100a 256-bit v8 ld/st halving wavefront count (-0.8us). All other
// axes (grid shape x4, per-thread MLP, occupancy, CTA count) measured neutral
// or regressive; remaining wall time is launch ramp + graph replay. Terminal.

#define GAMMA 0.1f

__global__ void __launch_bounds__(512) scale_v_kernel(const float* __restrict__ v,
                                                      float* __restrict__ out,
                                                      int n8) {
    int i = blockIdx.x * 512 + threadIdx.x;
    if (i < n8) {
        const float* src = v + (size_t)i * 8;
        float* dst = out + (size_t)i * 8;
        float a0, a1, a2, a3, a4, a5, a6, a7;
        asm volatile(
            "ld.global.nc.v8.f32 {%0,%1,%2,%3,%4,%5,%6,%7}, [%8];"
            : "=f"(a0), "=f"(a1), "=f"(a2), "=f"(a3),
              "=f"(a4), "=f"(a5), "=f"(a6), "=f"(a7)
            : "l"(src));
        a0 = -GAMMA * a0; a1 = -GAMMA * a1; a2 = -GAMMA * a2; a3 = -GAMMA * a3;
        a4 = -GAMMA * a4; a5 = -GAMMA * a5; a6 = -GAMMA * a6; a7 = -GAMMA * a7;
        asm volatile(
            "st.global.v8.f32 [%0], {%1,%2,%3,%4,%5,%6,%7,%8};"
            :: "l"(dst),
               "f"(a0), "f"(a1), "f"(a2), "f"(a3),
               "f"(a4), "f"(a5), "f"(a6), "f"(a7)
            : "memory");
    }
}

// Tail safety for out_size % 8 != 0 (not hit for this shape: 200000 % 8 == 0).
__global__ void scale_v_tail_kernel(const float* __restrict__ v,
                                    float* __restrict__ out,
                                    int start, int n) {
    int i = start + blockIdx.x * blockDim.x + threadIdx.x;
    if (i < n) out[i] = -GAMMA * v[i];
}

extern "C" void kernel_launch(void* const* d_in, const int* in_sizes, int n_in,
                              void* d_out, int out_size) {
    // metadata order: x, v, src, dst
    const float* v = (const float*)d_in[1];
    float* out = (float*)d_out;

    int n = out_size;      // 200000
    int n8 = n / 8;        // 25000
    int tail = n - n8 * 8; // 0 for this shape

    const int TPB = 512;
    if (n8 > 0) {
        int blocks = (n8 + TPB - 1) / TPB;   // 49 -> single wave
        scale_v_kernel<<<blocks, TPB>>>(v, out, n8);
    }
    if (tail > 0) {
        int blocks = (tail + 255) / 256;
        scale_v_tail_kernel<<<blocks, 256>>>(v, out, n8 * 8, n);
    }
}